// round 6
// baseline (speedup 1.0000x reference)
#include <cuda_runtime.h>
#include <cuda_bf16.h>

#define NIDS       33                  // ids 0..32 (0 = background)
#define NBINS      1089                // 33*33
#define THREADS    512                 // 16 warps per CTA
#define NWARPS     16
#define CNT_STRIDE 20                  // bytes per bin (16 used + 4 pad; 5 words, coprime w/ 32 banks)
#define CNT_BYTES  21792               // NBINS*20 = 21780, padded to /16
#define NREP       16                  // replicated global histograms

// Scratch (zero at load; finalize block resets after every call)
__device__ int          g_rep[NREP][NBINS];
__device__ unsigned int g_ticket;

__device__ __forceinline__ void bump(unsigned char* cnt, int w, unsigned mask_in, int bin) {
    unsigned m = __match_any_sync(mask_in, bin);        // lanes with equal bin
    unsigned lane_bit = 1u << (threadIdx.x & 31);
    if ((m & (lane_bit - 1u)) == 0u)                    // lowest matching lane = leader
        cnt[bin * CNT_STRIDE + w] += (unsigned char)__popc(m);
}

__global__ void __launch_bounds__(THREADS, 2)
fused_iou_kernel(const float4* __restrict__ p4, const float4* __restrict__ t4,
                 int n4,
                 const float* __restrict__ pf, const float* __restrict__ tf,
                 int n, float* __restrict__ out, int nblocks)
{
    __shared__ __align__(16) unsigned char cnt[CNT_BYTES];  // [bin][warp] bytes
    __shared__ float psum[NIDS], tsum[NIDS], part[NIDS];
    __shared__ int   s_last;

    int tid  = threadIdx.x;
    int w    = tid >> 5;

    // ---- zero byte counters ----
    {
        uint4* z4 = (uint4*)cnt;
        #pragma unroll 3
        for (int i = tid; i < CNT_BYTES / 16; i += THREADS)
            z4[i] = make_uint4(0u, 0u, 0u, 0u);
    }
    __syncthreads();

    int gid    = blockIdx.x * THREADS + tid;
    int stride = gridDim.x * THREADS;

    // ---- main loop: match-aggregated, non-atomic per-warp byte counters ----
    int i = gid;
    for (; i + stride < n4; i += 2 * stride) {
        float4 Pa = p4[i],          Ta = t4[i];
        float4 Pb = p4[i + stride], Tb = t4[i + stride];
        unsigned act = __activemask();
        bump(cnt, w, act, (int)fmaf(Pa.x, 33.0f, Ta.x));  // bin = 33*p + t (exact fp32)
        bump(cnt, w, act, (int)fmaf(Pa.y, 33.0f, Ta.y));
        bump(cnt, w, act, (int)fmaf(Pa.z, 33.0f, Ta.z));
        bump(cnt, w, act, (int)fmaf(Pa.w, 33.0f, Ta.w));
        bump(cnt, w, act, (int)fmaf(Pb.x, 33.0f, Tb.x));
        bump(cnt, w, act, (int)fmaf(Pb.y, 33.0f, Tb.y));
        bump(cnt, w, act, (int)fmaf(Pb.z, 33.0f, Tb.z));
        bump(cnt, w, act, (int)fmaf(Pb.w, 33.0f, Tb.w));
    }
    if (i < n4) {
        float4 P = p4[i], T = t4[i];
        unsigned act = __activemask();
        bump(cnt, w, act, (int)fmaf(P.x, 33.0f, T.x));
        bump(cnt, w, act, (int)fmaf(P.y, 33.0f, T.y));
        bump(cnt, w, act, (int)fmaf(P.z, 33.0f, T.z));
        bump(cnt, w, act, (int)fmaf(P.w, 33.0f, T.w));
    }
    __syncthreads();

    // ---- flush: per bin, dp4a-sum the 16 warp bytes, add to replicated hist ----
    int rep = blockIdx.x & (NREP - 1);
    for (int b = tid; b < NBINS; b += THREADS) {
        const unsigned int* wp = (const unsigned int*)(cnt + b * CNT_STRIDE);
        unsigned int s = __dp4a(wp[0], 0x01010101u, 0u)
                       + __dp4a(wp[1], 0x01010101u, 0u)
                       + __dp4a(wp[2], 0x01010101u, 0u)
                       + __dp4a(wp[3], 0x01010101u, 0u);
        if (s) atomicAdd(&g_rep[rep][b], (int)s);
    }
    __threadfence();

    // ---- ticket: last block finalizes ----
    if (tid == 0) {
        unsigned int t = atomicAdd(&g_ticket, 1u);
        s_last = (t == (unsigned int)(nblocks - 1));
    }
    __syncthreads();
    if (!s_last) return;

    int* h = (int*)cnt;   // reuse counter smem for the final histogram (post-sync)

    for (int b = tid; b < NBINS; b += THREADS) {
        int s = 0;
        #pragma unroll
        for (int r = 0; r < NREP; r++) { s += g_rep[r][b]; g_rep[r][b] = 0; }
        h[b] = s;
    }
    __syncthreads();
    if (tid == 0) {
        for (int k = n4 * 4; k < n; k++)               // scalar tail (n % 4)
            h[(int)fmaf(pf[k], 33.0f, tf[k])]++;
        g_ticket = 0u;
    }
    __syncthreads();

    if (tid < NIDS) {
        int s = 0;
        #pragma unroll
        for (int m = 0; m < NIDS; m++) s += h[tid * NIDS + m];
        psum[tid] = (float)s;
    } else if (tid >= 64 && tid < 64 + NIDS) {
        int m = tid - 64, s = 0;
        #pragma unroll
        for (int nn = 0; nn < NIDS; nn++) s += h[nn * NIDS + m];
        tsum[m] = (float)s;
    }
    __syncthreads();

    if (tid >= 1 && tid <= 32) {
        float pn = psum[tid];
        float max_iou = 0.0f;
        #pragma unroll
        for (int m = 1; m < NIDS; m++) {
            float inter = (float)h[tid * NIDS + m];
            float uni   = pn + tsum[m] - inter;
            float iou   = (uni > 0.0f) ? (inter / uni) : 0.0f;
            max_iou = fmaxf(max_iou, iou);
        }
        part[tid] = 1.0f - max_iou;
    }
    __syncthreads();

    if (tid == 0) {
        float loss = 0.0f;
        for (int nn = 1; nn <= 32; nn++) loss += part[nn];
        double sp = 0.0, st = 0.0;                      // exact dummy term
        for (int id = 1; id < NIDS; id++) {
            sp += (double)id * (double)psum[id];
            st += (double)id * (double)tsum[id];
        }
        loss += (float)((sp + st) * 1e-12);
        out[0] = loss;
    }
}

extern "C" void kernel_launch(void* const* d_in, const int* in_sizes, int n_in,
                              void* d_out, int out_size) {
    const float* pred  = (const float*)d_in[0];
    const float* truem = (const float*)d_in[1];
    float* out = (float*)d_out;
    int n  = in_sizes[0];
    int n4 = n / 4;

    int sm_count = 148;
    cudaDeviceGetAttribute(&sm_count, cudaDevAttrMultiProcessorCount, 0);
    int blocks = sm_count * 2;   // 2 CTAs/SM (21.8 KB smem each), 32 warps/SM

    fused_iou_kernel<<<blocks, THREADS>>>(
        (const float4*)pred, (const float4*)truem, n4,
        pred, truem, n, out, blocks);
}

// round 7
// speedup vs baseline: 2.3867x; 2.3867x over previous
#include <cuda_runtime.h>
#include <cuda_bf16.h>

#define NIDS    33                 // ids 0..32 (0 = background)
#define NBINS   1089               // 33*33
#define THREADS 512
#define NREP    16                 // replicated global histograms

// Scratch (zero at load; finalize block resets after every call)
__device__ int          g_rep[NREP][NBINS];
__device__ unsigned int g_ticket;

__global__ void __launch_bounds__(THREADS, 3)
fused_iou_kernel(const float4* __restrict__ p4, const float4* __restrict__ t4,
                 int n4,
                 const float* __restrict__ pf, const float* __restrict__ tf,
                 int n, float* __restrict__ out, int nblocks)
{
    __shared__ int   sh[NBINS];
    __shared__ float psum[NIDS], tsum[NIDS], part[NIDS];
    __shared__ int   s_last;

    int tid = threadIdx.x;
    for (int b = tid; b < NBINS; b += THREADS) sh[b] = 0;
    __syncthreads();

    int gid    = blockIdx.x * THREADS + tid;
    int stride = gridDim.x * THREADS;

    // ---- main loop: unroll x3, 6 independent front-batched LDG.128 ----
    int i = gid;
    for (; i + 2 * stride < n4; i += 3 * stride) {
        float4 P0 = p4[i];
        float4 T0 = t4[i];
        float4 P1 = p4[i + stride];
        float4 T1 = t4[i + stride];
        float4 P2 = p4[i + 2 * stride];
        float4 T2 = t4[i + 2 * stride];
        atomicAdd(&sh[(int)fmaf(P0.x, 33.0f, T0.x)], 1);  // bin = 33*p + t (exact fp32)
        atomicAdd(&sh[(int)fmaf(P0.y, 33.0f, T0.y)], 1);
        atomicAdd(&sh[(int)fmaf(P0.z, 33.0f, T0.z)], 1);
        atomicAdd(&sh[(int)fmaf(P0.w, 33.0f, T0.w)], 1);
        atomicAdd(&sh[(int)fmaf(P1.x, 33.0f, T1.x)], 1);
        atomicAdd(&sh[(int)fmaf(P1.y, 33.0f, T1.y)], 1);
        atomicAdd(&sh[(int)fmaf(P1.z, 33.0f, T1.z)], 1);
        atomicAdd(&sh[(int)fmaf(P1.w, 33.0f, T1.w)], 1);
        atomicAdd(&sh[(int)fmaf(P2.x, 33.0f, T2.x)], 1);
        atomicAdd(&sh[(int)fmaf(P2.y, 33.0f, T2.y)], 1);
        atomicAdd(&sh[(int)fmaf(P2.z, 33.0f, T2.z)], 1);
        atomicAdd(&sh[(int)fmaf(P2.w, 33.0f, T2.w)], 1);
    }
    for (; i < n4; i += stride) {
        float4 P = p4[i], T = t4[i];
        atomicAdd(&sh[(int)fmaf(P.x, 33.0f, T.x)], 1);
        atomicAdd(&sh[(int)fmaf(P.y, 33.0f, T.y)], 1);
        atomicAdd(&sh[(int)fmaf(P.z, 33.0f, T.z)], 1);
        atomicAdd(&sh[(int)fmaf(P.w, 33.0f, T.w)], 1);
    }
    __syncthreads();

    // ---- flush block hist into replicated global hists ----
    int rep = blockIdx.x & (NREP - 1);
    for (int b = tid; b < NBINS; b += THREADS) {
        int v = sh[b];
        if (v) atomicAdd(&g_rep[rep][b], v);
    }
    __threadfence();

    // ---- ticket: last block finalizes ----
    if (tid == 0) {
        unsigned int t = atomicAdd(&g_ticket, 1u);
        s_last = (t == (unsigned int)(nblocks - 1));
    }
    __syncthreads();
    if (!s_last) return;

    // reuse sh as the final histogram
    for (int b = tid; b < NBINS; b += THREADS) {
        int s = 0;
        #pragma unroll
        for (int r = 0; r < NREP; r++) { s += g_rep[r][b]; g_rep[r][b] = 0; }
        sh[b] = s;
    }
    __syncthreads();
    if (tid == 0) {
        for (int k = n4 * 4; k < n; k++)               // scalar tail (n % 4)
            sh[(int)fmaf(pf[k], 33.0f, tf[k])]++;
        g_ticket = 0u;
    }
    __syncthreads();

    if (tid < NIDS) {
        int s = 0;
        #pragma unroll
        for (int m = 0; m < NIDS; m++) s += sh[tid * NIDS + m];
        psum[tid] = (float)s;
    } else if (tid >= 64 && tid < 64 + NIDS) {
        int m = tid - 64, s = 0;
        #pragma unroll
        for (int nn = 0; nn < NIDS; nn++) s += sh[nn * NIDS + m];
        tsum[m] = (float)s;
    }
    __syncthreads();

    if (tid >= 1 && tid <= 32) {
        float pn = psum[tid];
        float max_iou = 0.0f;
        #pragma unroll
        for (int m = 1; m < NIDS; m++) {
            float inter = (float)sh[tid * NIDS + m];
            float uni   = pn + tsum[m] - inter;
            float iou   = (uni > 0.0f) ? (inter / uni) : 0.0f;
            max_iou = fmaxf(max_iou, iou);
        }
        part[tid] = 1.0f - max_iou;
    }
    __syncthreads();

    if (tid == 0) {
        float loss = 0.0f;
        for (int nn = 1; nn <= 32; nn++) loss += part[nn];
        double sp = 0.0, st = 0.0;                      // exact dummy term
        for (int id = 1; id < NIDS; id++) {
            sp += (double)id * (double)psum[id];
            st += (double)id * (double)tsum[id];
        }
        loss += (float)((sp + st) * 1e-12);
        out[0] = loss;
    }
}

extern "C" void kernel_launch(void* const* d_in, const int* in_sizes, int n_in,
                              void* d_out, int out_size) {
    const float* pred  = (const float*)d_in[0];
    const float* truem = (const float*)d_in[1];
    float* out = (float*)d_out;
    int n  = in_sizes[0];
    int n4 = n / 4;

    int sm_count = 148;
    cudaDeviceGetAttribute(&sm_count, cudaDevAttrMultiProcessorCount, 0);
    int blocks = sm_count * 3;   // 3 CTAs/SM x 512 thr = 48 warps/SM (occ 75%)

    fused_iou_kernel<<<blocks, THREADS>>>(
        (const float4*)pred, (const float4*)truem, n4,
        pred, truem, n, out, blocks);
}